// round 8
// baseline (speedup 1.0000x reference)
#include <cuda_runtime.h>
#include <cuda_fp16.h>
#include <math.h>
#include <stdint.h>

// Problem constants
#define BB    16
#define CC    64
#define HWSZ  4096
#define NPIX  65536
#define KK    1024
#define DD    64
#define NEL   4194304
#define GATHER_BLOCKS 4096     // NEL / 4 / 256

// Device scratch
__device__ __align__(16) int    g_idx[NPIX];
__device__ float                g_counts[KK];
__device__ float                g_cnorm[KK];
__device__ float                g_part[GATHER_BLOCKS];
__device__ __align__(16) __half g_ch[KK * DD];   // [-c] fp16: [8 chunks][64 d][64 pairs][2]
__device__ int                  g_cnmax_i;       // bits of max cn (monotonic, deterministic)

// ---------------------------------------------------------------------------
// Kernel 1: prep — exact cn, negated fp16 pair-interleaved codebook, stats
// ---------------------------------------------------------------------------
__global__ void prep_kernel(const float* __restrict__ cb) {
    int k = blockIdx.x * 256 + threadIdx.x;
    if (k >= KK) return;
    const int ch   = k >> 7;          // chunk
    const int pair = (k & 127) >> 1;
    const int lane = k & 1;
    float s = 0.f;
    #pragma unroll
    for (int d = 0; d < DD; d++) {
        float v = cb[k * DD + d];
        s = __fadd_rn(s, __fmul_rn(v, v));   // reference-exact cn
        g_ch[(((ch * 64 + d) * 64) + pair) * 2 + lane] = __float2half(-v);
    }
    g_cnorm[k]  = s;
    g_counts[k] = 0.f;
    atomicMax(&g_cnmax_i, __float_as_int(s));   // positive floats: int order ok
}

// ---------------------------------------------------------------------------
// Kernel 2: HFMA2 coarse keys + margin filter + inline exact-fp32 refine
// 256 threads, 128 pixels/block; thread (tx,ty) owns px tx*8..+7, codes ty*8..+7
// smem: xs f32[64][128] | xd h2[64][128] | cs h2[64][64] | cns f32[1024] | nss[128]
// ---------------------------------------------------------------------------
extern __shared__ char smraw[];

__global__ void __launch_bounds__(256, 2)
coarse_kernel(const float* __restrict__ in, const float* __restrict__ cb) {
    float*   xs  = (float*)smraw;                  // 32768 B
    __half2* xd  = (__half2*)(smraw + 32768);      // 32768 B
    __half2* cs  = (__half2*)(smraw + 65536);      // 16384 B
    float*   cns = (float*)(smraw + 81920);        // 4096 B
    float*   nss = (float*)(smraw + 86016);        // 512 B   (total 86528)

    const int tid = threadIdx.x;
    const int tx  = tid & 15;
    const int ty  = tid >> 4;

    const int n0  = blockIdx.x * 128;
    const int b   = n0 >> 12;
    const int hw0 = n0 & 4095;
    const float* xin = in + (size_t)b * CC * HWSZ + hw0;

    // x tile (fp32 + duplicated fp16 pairs), cn table
    for (int i = tid; i < 8192; i += 256) {
        int d = i >> 7, p = i & 127;
        float v = xin[(size_t)d * HWSZ + p];
        xs[d * 128 + p] = v;
        xd[d * 128 + p] = __float2half2_rn(v);
    }
    for (int i = tid; i < KK; i += 256) cns[i] = g_cnorm[i];
    __syncthreads();

    if (tid < 128) {   // exact ||x||^2 (reference rounding)
        float s = 0.f;
        #pragma unroll
        for (int d = 0; d < DD; d++) {
            float v = xs[d * 128 + tid];
            s = __fadd_rn(s, __fmul_rn(v, v));
        }
        nss[tid] = s;
    }
    __syncthreads();

    const float cnmax = __int_as_float(g_cnmax_i);

    // per-pixel running min, margin, and exact-best u64 key
    float m[8], Mg[8];
    unsigned long long best[8];
    #pragma unroll
    for (int i = 0; i < 8; i++) {
        float ns = nss[tx * 8 + i];
        m[i]    = 3.4e38f;
        Mg[i]   = 0.08f * sqrtf(ns * cnmax) + cnmax + 1e-4f;
        best[i] = ~0ull;
    }

    for (int ch = 0; ch < 8; ch++) {
        __syncthreads();
        // load code chunk: 64 d x 64 pairs = 16KB (coalesced uint4)
        {
            const uint4* src = (const uint4*)((const char*)g_ch + ch * 16384);
            uint4* dst = (uint4*)cs;
            #pragma unroll
            for (int i = 0; i < 4; i++) dst[tid + i * 256] = src[tid + i * 256];
        }
        __syncthreads();

        __half2 acc[8][4];
        #pragma unroll
        for (int i = 0; i < 8; i++)
            #pragma unroll
            for (int j = 0; j < 4; j++) acc[i][j] = __float2half2_rn(0.f);

        // key accumulation: acc[i][j] += x_i * (-c)  (fp16x2, 2 codes per reg)
        #pragma unroll 4
        for (int d = 0; d < 64; d++) {
            uint4 xa = *(const uint4*)&xd[d * 128 + tx * 8];
            uint4 xb = *(const uint4*)&xd[d * 128 + tx * 8 + 4];
            uint4 cv = *(const uint4*)&cs[d * 64 + ty * 4];
            __half2 xv[8], cw[4];
            *(uint4*)&xv[0] = xa;
            *(uint4*)&xv[4] = xb;
            *(uint4*)&cw[0] = cv;
            #pragma unroll
            for (int i = 0; i < 8; i++)
                #pragma unroll
                for (int j = 0; j < 4; j++)
                    acc[i][j] = __hfma2(xv[i], cw[j], acc[i][j]);
        }

        // epilogue: fold, update running min, detect + refine rare candidates
        #pragma unroll
        for (int i = 0; i < 8; i++) {
            __half2 r = __hmin2(__hmin2(acc[i][0], acc[i][1]),
                                __hmin2(acc[i][2], acc[i][3]));
            float mn = fminf(__low2float(r), __high2float(r));
            if (mn < m[i]) m[i] = mn;
            float thr = m[i] + Mg[i];
            if (mn < thr) {
                const int px = tx * 8 + i;
                const float ns = nss[px];
                #pragma unroll
                for (int j = 0; j < 4; j++) {
                    float k0 = __low2float(acc[i][j]);
                    float k1 = __high2float(acc[i][j]);
                    #pragma unroll
                    for (int e = 0; e < 2; e++) {
                        float kv = e ? k1 : k0;
                        if (kv < thr) {
                            int n = ch * 128 + ty * 8 + j * 2 + e;
                            const float4* cr = (const float4*)(cb + (size_t)n * DD);
                            float a2 = 0.f;
                            #pragma unroll
                            for (int w = 0; w < 16; w++) {
                                float4 c = __ldg(&cr[w]);
                                a2 = __fmaf_rn(xs[(w * 4 + 0) * 128 + px], c.x, a2);
                                a2 = __fmaf_rn(xs[(w * 4 + 1) * 128 + px], c.y, a2);
                                a2 = __fmaf_rn(xs[(w * 4 + 2) * 128 + px], c.z, a2);
                                a2 = __fmaf_rn(xs[(w * 4 + 3) * 128 + px], c.w, a2);
                            }
                            // bit-exact reference score: fl(fl(ns+cn) - fl(2*dot))
                            float sE = __fsub_rn(__fadd_rn(ns, cns[n]),
                                                 __fmul_rn(2.f, a2));
                            unsigned long long key =
                                ((unsigned long long)__float_as_uint(sE) << 32) |
                                (unsigned)n;
                            if (key < best[i]) best[i] = key;
                        }
                    }
                }
            }
        }
    }

    // cross-thread (over ty) u64 min reduction per pixel; reuse smem
    __syncthreads();
    unsigned long long* rb = (unsigned long long*)smraw;   // [16][128] = 16KB
    #pragma unroll
    for (int i = 0; i < 8; i++) rb[ty * 128 + tx * 8 + i] = best[i];
    __syncthreads();
    if (tid < 128) {
        unsigned long long bk = rb[tid];
        #pragma unroll
        for (int t = 1; t < 16; t++) {
            unsigned long long v = rb[t * 128 + tid];
            if (v < bk) bk = v;
        }
        int bidx = (int)(bk & 0xffffffffull);
        g_idx[n0 + tid] = bidx;
        atomicAdd(&g_counts[bidx], 1.0f);   // integer-valued: deterministic
    }
}

// ---------------------------------------------------------------------------
// Kernel 3: gather quantized output + per-block loss partial.
// Loads vectorized; outq = out+1 (4 mod 16) so stores stay scalar.
// ---------------------------------------------------------------------------
__global__ void gather_loss_kernel(const float* __restrict__ in,
                                   const float* __restrict__ cb,
                                   float* __restrict__ outq) {
    const int tid = threadIdx.x;
    const int e   = (blockIdx.x * 256 + tid) * 4;

    int b  = e >> 18;
    int r  = e & 262143;
    int c  = r >> 12;
    int hw = r & 4095;           // multiple of 4
    const int4 gi = *(const int4*)&g_idx[(b << 12) | hw];

    float4 x = *(const float4*)(in + e);
    float q0 = __ldg(&cb[gi.x * DD + c]);
    float q1 = __ldg(&cb[gi.y * DD + c]);
    float q2 = __ldg(&cb[gi.z * DD + c]);
    float q3 = __ldg(&cb[gi.w * DD + c]);

    float d0 = q0 - x.x, d1 = q1 - x.y, d2 = q2 - x.z, d3 = q3 - x.w;
    outq[e + 0] = x.x + d0;
    outq[e + 1] = x.y + d1;
    outq[e + 2] = x.z + d2;
    outq[e + 3] = x.w + d3;
    float part = d0 * d0 + d1 * d1 + d2 * d2 + d3 * d3;

    #pragma unroll
    for (int o2 = 16; o2; o2 >>= 1)
        part += __shfl_xor_sync(0xffffffffu, part, o2);
    __shared__ float ws[8];
    if ((tid & 31) == 0) ws[tid >> 5] = part;
    __syncthreads();
    if (tid == 0) {
        float s = 0.f;
        #pragma unroll
        for (int w = 0; w < 8; w++) s += ws[w];
        g_part[blockIdx.x] = s;
    }
}

// ---------------------------------------------------------------------------
// Kernel 4: finalize loss + perplexity
// ---------------------------------------------------------------------------
__global__ void finalize_kernel(const float* __restrict__ beta,
                                float* __restrict__ loss_out,
                                float* __restrict__ pp_out) {
    const int t = threadIdx.x;   // 1024

    float ls = 0.f;
    #pragma unroll
    for (int i = 0; i < GATHER_BLOCKS / 1024; i++)
        ls += g_part[t * (GATHER_BLOCKS / 1024) + i];

    float em  = g_counts[t] * (1.0f / (float)NPIX);
    float ent = em * logf(em + 1e-10f);

    #pragma unroll
    for (int o = 16; o; o >>= 1) {
        ls  += __shfl_xor_sync(0xffffffffu, ls, o);
        ent += __shfl_xor_sync(0xffffffffu, ent, o);
    }
    __shared__ float wl[32], we[32];
    if ((t & 31) == 0) { wl[t >> 5] = ls; we[t >> 5] = ent; }
    __syncthreads();
    if (t == 0) {
        float tl = 0.f, te = 0.f;
        #pragma unroll
        for (int w = 0; w < 32; w++) { tl += wl[w]; te += we[w]; }
        float mean = tl / (float)NEL;
        *loss_out = (1.0f + *beta) * 10.0f * mean;   // KLD_SCALE = 10
        *pp_out   = expf(-te);
    }
}

// ---------------------------------------------------------------------------
// Launch
// ---------------------------------------------------------------------------
extern "C" void kernel_launch(void* const* d_in, const int* in_sizes, int n_in,
                              void* d_out, int out_size) {
    const float* in   = nullptr;
    const float* cb   = nullptr;
    const float* beta = nullptr;
    for (int i = 0; i < n_in; i++) {
        if      (in_sizes[i] == NEL)     in   = (const float*)d_in[i];
        else if (in_sizes[i] == KK * DD) cb   = (const float*)d_in[i];
        else if (in_sizes[i] == 1)       beta = (const float*)d_in[i];
    }

    float* out      = (float*)d_out;
    float* loss_out = out;
    float* q_out    = out + 1;
    float* pp_out   = out + (out_size - 1);

    const int smem_bytes = 86528;
    cudaFuncSetAttribute(coarse_kernel,
                         cudaFuncAttributeMaxDynamicSharedMemorySize, smem_bytes);

    prep_kernel<<<(KK + 255) / 256, 256>>>(cb);
    coarse_kernel<<<NPIX / 128, 256, smem_bytes>>>(in, cb);
    gather_loss_kernel<<<GATHER_BLOCKS, 256>>>(in, cb, q_out);
    finalize_kernel<<<1, 1024>>>(beta, loss_out, pp_out);
}